// round 7
// baseline (speedup 1.0000x reference)
#include <cuda_runtime.h>
#include <math.h>
#include <stdint.h>

#define N_NODES 50000
#define N_EDGES 1600000
#define E_TOT   1650000   // + self loops
#define NEG_SLOPE 0.2f

#define SBLK 256
#define NBLOCKS_SCAN ((N_NODES + SBLK - 1) / SBLK)   // 196
#define STAGE 128      // per-warp smem staging capacity (deg is Poisson(33))

// ---------------- scratch (device globals; only referenced from device code) ----------------
__device__ __align__(16) float g_xl1[N_NODES * 128];
__device__ __align__(16) float g_h1 [N_NODES * 128];
__device__ __align__(16) float g_xl2[N_NODES * 64];
__device__ __align__(16) float g_as1[N_NODES * 2];
__device__ __align__(16) float g_ad1[N_NODES * 2];
__device__ __align__(16) float g_as2[N_NODES];
__device__ __align__(16) float g_ad2[N_NODES];

__device__ __align__(16) int   g_deg [N_NODES];
__device__ __align__(16) int   g_ptr [N_NODES + 1];
__device__ __align__(16) int   g_work[N_NODES];
__device__ __align__(16) int   g_src_csr[E_TOT];
__device__ __align__(16) float g_e_csr[E_TOT * 2];   // fallback only (deg > STAGE)
__device__ __align__(16) int   g_bsum[NBLOCKS_SCAN];
__device__ __align__(16) int   g_boff[NBLOCKS_SCAN];

__device__ int g_e64;

// ---------------- helpers ----------------
__device__ __forceinline__ float lrelu(float x) {
    return x >= 0.0f ? x : NEG_SLOPE * x;
}

__device__ __forceinline__ void edge_sd(const void* ei, int is64, int e, int& s, int& d) {
    if (e >= N_EDGES) { s = d = e - N_EDGES; return; }
    if (is64) {
        const long long* p = (const long long*)ei;
        s = (int)p[e];
        d = (int)p[N_EDGES + e];
    } else {
        const int* p = (const int*)ei;
        s = p[e];
        d = p[N_EDGES + e];
    }
}

__device__ __forceinline__ int warp_incl_scan(int v, int lane) {
#pragma unroll
    for (int off = 1; off < 32; off <<= 1) {
        int n = __shfl_up_sync(0xffffffff, v, off);
        if (lane >= off) v += n;
    }
    return v;
}

// ---------------- graph preprocessing ----------------
// zero degrees + detect int64/int32 serialization in one kernel
__global__ void prep_kernel(const long long* ei) {
    int i = blockIdx.x * blockDim.x + threadIdx.x;
    if (i < N_NODES) g_deg[i] = 0;
    if (blockIdx.x == 0) {
        __shared__ int bad;
        if (threadIdx.x == 0) bad = 0;
        __syncthreads();
        long long v = ei[threadIdx.x];
        if (v < 0 || v >= N_NODES) bad = 1;
        __syncthreads();
        if (threadIdx.x == 0) g_e64 = bad ? 0 : 1;
    }
}

__global__ void hist_kernel(const void* __restrict__ ei) {
    int e = blockIdx.x * blockDim.x + threadIdx.x;
    if (e >= E_TOT) return;
    int s, d; edge_sd(ei, g_e64, e, s, d);
    atomicAdd(&g_deg[d], 1);
}

__global__ void scan_partial_kernel() {
    int i = blockIdx.x * SBLK + threadIdx.x;
    int v = (i < N_NODES) ? g_deg[i] : 0;
    __shared__ int ws[8];
    int lane = threadIdx.x & 31, wid = threadIdx.x >> 5;
    int s = v;
#pragma unroll
    for (int off = 16; off; off >>= 1) s += __shfl_xor_sync(0xffffffff, s, off);
    if (lane == 0) ws[wid] = s;
    __syncthreads();
    if (threadIdx.x == 0) {
        int t = 0;
#pragma unroll
        for (int w = 0; w < 8; w++) t += ws[w];
        g_bsum[blockIdx.x] = t;
    }
}

__global__ void scan_bsum_kernel() {
    int t = threadIdx.x;
    int v = (t < NBLOCKS_SCAN) ? g_bsum[t] : 0;
    __shared__ int ws[8];
    int lane = t & 31, wid = t >> 5;
    int inc = warp_incl_scan(v, lane);
    if (lane == 31) ws[wid] = inc;
    __syncthreads();
    if (wid == 0) {
        int wv = (lane < 8) ? ws[lane] : 0;
        int winc = warp_incl_scan(wv, lane);
        if (lane < 8) ws[lane] = winc;
    }
    __syncthreads();
    int excl = inc - v + (wid ? ws[wid - 1] : 0);
    if (t < NBLOCKS_SCAN) g_boff[t] = excl;
    if (t == NBLOCKS_SCAN - 1) g_ptr[N_NODES] = excl + v;
}

__global__ void scan_final_kernel() {
    int i = blockIdx.x * SBLK + threadIdx.x;
    int v = (i < N_NODES) ? g_deg[i] : 0;
    __shared__ int ws[8];
    int lane = threadIdx.x & 31, wid = threadIdx.x >> 5;
    int inc = warp_incl_scan(v, lane);
    if (lane == 31) ws[wid] = inc;
    __syncthreads();
    if (wid == 0) {
        int wv = (lane < 8) ? ws[lane] : 0;
        int winc = warp_incl_scan(wv, lane);
        if (lane < 8) ws[lane] = winc;
    }
    __syncthreads();
    int excl = inc - v + (wid ? ws[wid - 1] : 0) + g_boff[blockIdx.x];
    if (i < N_NODES) { g_ptr[i] = excl; g_work[i] = excl; }
}

__global__ void scatter_kernel(const void* __restrict__ ei) {
    int e = blockIdx.x * blockDim.x + threadIdx.x;
    if (e >= E_TOT) return;
    int s, d; edge_sd(ei, g_e64, e, s, d);
    int pos = atomicAdd(&g_work[d], 1);
    g_src_csr[pos] = s;
}

// ---------------- GEMM with fused attention-logit epilogue ----------------
// MODE 1: X = x -> g_xl1 (NCOL=128, H=2); epilogue writes g_as1/g_ad1.
// MODE 2: X = g_h1 -> g_xl2 (NCOL=64, H=1); epilogue writes g_as2/g_ad2.
template<int NCOL, int MODE>
__global__ void gemm_kernel(const float* __restrict__ Xext,
                            const float* __restrict__ W,
                            const float* __restrict__ att_src,
                            const float* __restrict__ att_dst) {
    const float* X   = (MODE == 1) ? Xext : g_h1;
    float*       out = (MODE == 1) ? g_xl1 : g_xl2;
    constexpr int NW = NCOL / 32;   // warps per block

    __shared__ float sX[32][128];
    __shared__ float red_s[32][NW];
    __shared__ float red_d[32][NW];
    const int row0 = blockIdx.x * 32;
    const int tid  = threadIdx.x;
    const int lane = tid & 31, wid = tid >> 5;

    for (int idx = tid; idx < 32 * 128; idx += NCOL) {
        int r = idx >> 7, c = idx & 127;
        int row = row0 + r;
        sX[r][c] = (row < N_NODES) ? X[row * 128 + c] : 0.0f;
    }
    __syncthreads();

    float acc[32];
#pragma unroll
    for (int r = 0; r < 32; r++) acc[r] = 0.0f;

    for (int k = 0; k < 128; k++) {
        float w = W[k * NCOL + tid];
#pragma unroll
        for (int r = 0; r < 32; r++) acc[r] += sX[r][k] * w;
    }

    // epilogue part 1: per-row attention partials, warp-reduced
    float asv = att_src[tid];
    float adv = att_dst[tid];
#pragma unroll
    for (int r = 0; r < 32; r++) {
        float ps = acc[r] * asv;
        float pd = acc[r] * adv;
#pragma unroll
        for (int off = 16; off; off >>= 1) {
            ps += __shfl_xor_sync(0xffffffff, ps, off);
            pd += __shfl_xor_sync(0xffffffff, pd, off);
        }
        if (lane == 0) { red_s[r][wid] = ps; red_d[r][wid] = pd; }
    }

    // store xl
#pragma unroll
    for (int r = 0; r < 32; r++) {
        int row = row0 + r;
        if (row < N_NODES) out[row * NCOL + tid] = acc[r];
    }
    __syncthreads();

    // epilogue part 2: combine warp partials per row
    if (tid < 32) {
        int row = row0 + tid;
        if (row < N_NODES) {
            if (MODE == 1) {
                // warps 0-1 = head 0 (cols 0-63), warps 2-3 = head 1
                g_as1[row * 2 + 0] = red_s[tid][0] + red_s[tid][1];
                g_as1[row * 2 + 1] = red_s[tid][2] + red_s[tid][3];
                g_ad1[row * 2 + 0] = red_d[tid][0] + red_d[tid][1];
                g_ad1[row * 2 + 1] = red_d[tid][2] + red_d[tid][3];
            } else {
                g_as2[row] = red_s[tid][0] + red_s[tid][1];
                g_ad2[row] = red_d[tid][0] + red_d[tid][1];
            }
        }
    }
}

// ---------------- fused softmax + aggregation (CSR, warp per dst node) ----------------
// Softmax shift dropped (logits O(1), softmax shift-invariant).
__global__ void fused1_kernel(const float* __restrict__ b1) {
    __shared__ int   s_src[8][STAGE];
    __shared__ float s_e  [8][STAGE * 2];
    int node = (blockIdx.x * blockDim.x + threadIdx.x) >> 5;
    int lane = threadIdx.x & 31;
    int wslot = (threadIdx.x >> 5);
    if (node >= N_NODES) return;
    int start = g_ptr[node], end = g_ptr[node + 1];
    int deg = end - start;
    bool sm = (deg <= STAGE);

    float ad0 = g_ad1[node * 2 + 0];
    float ad1 = g_ad1[node * 2 + 1];

    float den0 = 0.0f, den1 = 0.0f;
    for (int j = start + lane; j < end; j += 32) {
        int s = g_src_csr[j];
        float2 as = ((const float2*)g_as1)[s];
        float e0 = expf(lrelu(as.x + ad0));
        float e1 = expf(lrelu(as.y + ad1));
        if (sm) {
            int k = j - start;
            s_src[wslot][k] = s;
            s_e[wslot][k * 2 + 0] = e0;
            s_e[wslot][k * 2 + 1] = e1;
        } else {
            ((float2*)g_e_csr)[j] = make_float2(e0, e1);
        }
        den0 += e0; den1 += e1;
    }
#pragma unroll
    for (int off = 16; off; off >>= 1) {
        den0 += __shfl_xor_sync(0xffffffff, den0, off);
        den1 += __shfl_xor_sync(0xffffffff, den1, off);
    }
    int h = lane >> 4;
    float rden = 1.0f / (h ? den1 : den0);
    __syncwarp();

    float4 bv = ((const float4*)b1)[lane];
    float a0 = bv.x, a1 = bv.y, a2 = bv.z, a3 = bv.w;
    if (sm) {
#pragma unroll 4
        for (int k = 0; k < deg; k++) {
            int s = s_src[wslot][k];
            float alpha = s_e[wslot][k * 2 + h] * rden;
            float4 xv = ((const float4*)(g_xl1 + (size_t)s * 128))[lane];
            a0 += alpha * xv.x; a1 += alpha * xv.y;
            a2 += alpha * xv.z; a3 += alpha * xv.w;
        }
    } else {
        for (int j = start; j < end; j++) {
            int s = g_src_csr[j];
            float alpha = g_e_csr[j * 2 + h] * rden;
            float4 xv = ((const float4*)(g_xl1 + (size_t)s * 128))[lane];
            a0 += alpha * xv.x; a1 += alpha * xv.y;
            a2 += alpha * xv.z; a3 += alpha * xv.w;
        }
    }
    float4 r = make_float4(fmaxf(a0, 0.f), fmaxf(a1, 0.f), fmaxf(a2, 0.f), fmaxf(a3, 0.f));
    ((float4*)(g_h1 + (size_t)node * 128))[lane] = r;
}

__global__ void fused2_kernel(const float* __restrict__ b2, float* __restrict__ out) {
    __shared__ int   s_src[8][STAGE];
    __shared__ float s_e  [8][STAGE];
    int node = (blockIdx.x * blockDim.x + threadIdx.x) >> 5;
    int lane = threadIdx.x & 31;
    int wslot = (threadIdx.x >> 5);
    if (node >= N_NODES) return;
    int start = g_ptr[node], end = g_ptr[node + 1];
    int deg = end - start;
    bool sm = (deg <= STAGE);

    float adv = g_ad2[node];

    float den = 0.0f;
    for (int j = start + lane; j < end; j += 32) {
        int s = g_src_csr[j];
        float ev = expf(lrelu(g_as2[s] + adv));
        if (sm) {
            int k = j - start;
            s_src[wslot][k] = s;
            s_e[wslot][k] = ev;
        } else {
            g_e_csr[j] = ev;
        }
        den += ev;
    }
#pragma unroll
    for (int off = 16; off; off >>= 1)
        den += __shfl_xor_sync(0xffffffff, den, off);
    float rden = 1.0f / den;
    __syncwarp();

    float2 bv = ((const float2*)b2)[lane];
    float a0 = bv.x, a1 = bv.y;
    if (sm) {
#pragma unroll 4
        for (int k = 0; k < deg; k++) {
            int s = s_src[wslot][k];
            float alpha = s_e[wslot][k] * rden;
            float2 xv = ((const float2*)(g_xl2 + (size_t)s * 64))[lane];
            a0 += alpha * xv.x; a1 += alpha * xv.y;
        }
    } else {
        for (int j = start; j < end; j++) {
            int s = g_src_csr[j];
            float alpha = g_e_csr[j] * rden;
            float2 xv = ((const float2*)(g_xl2 + (size_t)s * 64))[lane];
            a0 += alpha * xv.x; a1 += alpha * xv.y;
        }
    }
    float2 r = make_float2(fmaxf(a0, 0.f), fmaxf(a1, 0.f));
    ((float2*)(out + (size_t)node * 64))[lane] = r;
}

// ---------------- launch ----------------
extern "C" void kernel_launch(void* const* d_in, const int* in_sizes, int n_in,
                              void* d_out, int out_size) {
    const float *x = 0, *W1 = 0, *W2 = 0;
    const void  *ei = 0;
    const float *v128[3] = {0, 0, 0};
    const float *v64 [3] = {0, 0, 0};
    int n128 = 0, n64 = 0;
    for (int i = 0; i < n_in; i++) {
        int sz = in_sizes[i];
        if      (sz == N_NODES * 128) x  = (const float*)d_in[i];
        else if (sz == 2 * N_EDGES)   ei = d_in[i];
        else if (sz == 128 * 128)     W1 = (const float*)d_in[i];
        else if (sz == 128 * 64)      W2 = (const float*)d_in[i];
        else if (sz == 128 && n128 < 3) v128[n128++] = (const float*)d_in[i];
        else if (sz == 64  && n64  < 3) v64 [n64++]  = (const float*)d_in[i];
    }
    const float* att_src1 = v128[0];
    const float* att_dst1 = v128[1];
    const float* b1       = v128[2];
    const float* att_src2 = v64[0];
    const float* att_dst2 = v64[1];
    const float* b2       = v64[2];
    float* out = (float*)d_out;

    const int TPB = 256;
    const int edge_blocks = (E_TOT + TPB - 1) / TPB;
    const int warp_blocks = (N_NODES * 32 + TPB - 1) / TPB;
    const int gemm_blocks = (N_NODES + 31) / 32;
    const int prep_blocks = (N_NODES + TPB - 1) / TPB;

    // fork/join: CSR chain on the capture (default) stream, gemm1 on s1.
    cudaStream_t s1;
    cudaStreamCreateWithFlags(&s1, cudaStreamNonBlocking);
    cudaEvent_t ev_fork, ev_gemm1;
    cudaEventCreateWithFlags(&ev_fork,  cudaEventDisableTiming);
    cudaEventCreateWithFlags(&ev_gemm1, cudaEventDisableTiming);

    cudaEventRecord(ev_fork, 0);
    cudaStreamWaitEvent(s1, ev_fork, 0);

    // branch A (capture stream): CSR by destination
    prep_kernel<<<prep_blocks, TPB>>>((const long long*)ei);
    hist_kernel<<<edge_blocks, TPB>>>(ei);
    scan_partial_kernel<<<NBLOCKS_SCAN, SBLK>>>();
    scan_bsum_kernel<<<1, 256>>>();
    scan_final_kernel<<<NBLOCKS_SCAN, SBLK>>>();
    scatter_kernel<<<edge_blocks, TPB>>>(ei);

    // branch B (s1): layer-1 GEMM + fused attention logits
    gemm_kernel<128, 1><<<gemm_blocks, 128, 0, s1>>>(x, W1, att_src1, att_dst1);
    cudaEventRecord(ev_gemm1, s1);
    cudaStreamWaitEvent(0, ev_gemm1, 0);

    // join: rest is sequential on the capture stream
    fused1_kernel<<<warp_blocks, TPB>>>(b1);
    gemm_kernel<64, 2><<<gemm_blocks, 64>>>(x, W2, att_src2, att_dst2);
    fused2_kernel<<<warp_blocks, TPB>>>(b2, out);

    cudaEventDestroy(ev_fork);
    cudaEventDestroy(ev_gemm1);
    cudaStreamDestroy(s1);
}

// round 8
// speedup vs baseline: 1.5246x; 1.5246x over previous
#include <cuda_runtime.h>
#include <math.h>
#include <stdint.h>

#define N_NODES 50000
#define N_EDGES 1600000
#define E_TOT   1650000   // + self loops
#define NEG_SLOPE 0.2f

#define SBLK 256
#define NBLOCKS_SCAN ((N_NODES + SBLK - 1) / SBLK)   // 196
#define STAGE 128        // per-warp smem staging capacity (deg is Poisson(33))
#define XPITCH 132       // padded smem row pitch (16B-aligned, bank-shifted)

// ---------------- scratch (device globals; only referenced from device code) ----------------
__device__ __align__(16) float g_xl1[N_NODES * 128];
__device__ __align__(16) float g_h1 [N_NODES * 128];
__device__ __align__(16) float g_xl2[N_NODES * 64];
__device__ __align__(16) float g_as1[N_NODES * 2];
__device__ __align__(16) float g_ad1[N_NODES * 2];
__device__ __align__(16) float g_as2[N_NODES];
__device__ __align__(16) float g_ad2[N_NODES];

__device__ __align__(16) int   g_deg [N_NODES];
__device__ __align__(16) int   g_ptr [N_NODES + 1];
__device__ __align__(16) int   g_work[N_NODES];
__device__ __align__(16) int   g_src_csr[E_TOT];
__device__ __align__(16) float g_e_csr[E_TOT * 2];   // fallback only (deg > STAGE)
__device__ __align__(16) int   g_bsum[NBLOCKS_SCAN];
__device__ __align__(16) int   g_boff[NBLOCKS_SCAN];

__device__ int g_e64;

// ---------------- helpers ----------------
__device__ __forceinline__ float lrelu(float x) {
    return x >= 0.0f ? x : NEG_SLOPE * x;
}

__device__ __forceinline__ void edge_sd(const void* ei, int is64, int e, int& s, int& d) {
    if (e >= N_EDGES) { s = d = e - N_EDGES; return; }
    if (is64) {
        const long long* p = (const long long*)ei;
        s = (int)p[e];
        d = (int)p[N_EDGES + e];
    } else {
        const int* p = (const int*)ei;
        s = p[e];
        d = p[N_EDGES + e];
    }
}

__device__ __forceinline__ int warp_incl_scan(int v, int lane) {
#pragma unroll
    for (int off = 1; off < 32; off <<= 1) {
        int n = __shfl_up_sync(0xffffffff, v, off);
        if (lane >= off) v += n;
    }
    return v;
}

// ---------------- graph preprocessing ----------------
__global__ void prep_kernel(const long long* ei) {
    int i = blockIdx.x * blockDim.x + threadIdx.x;
    if (i < N_NODES) g_deg[i] = 0;
    if (blockIdx.x == 0) {
        __shared__ int bad;
        if (threadIdx.x == 0) bad = 0;
        __syncthreads();
        long long v = ei[threadIdx.x];
        if (v < 0 || v >= N_NODES) bad = 1;
        __syncthreads();
        if (threadIdx.x == 0) g_e64 = bad ? 0 : 1;
    }
}

__global__ void hist_kernel(const void* __restrict__ ei) {
    int e = blockIdx.x * blockDim.x + threadIdx.x;
    if (e >= E_TOT) return;
    int s, d; edge_sd(ei, g_e64, e, s, d);
    atomicAdd(&g_deg[d], 1);
}

__global__ void scan_partial_kernel() {
    int i = blockIdx.x * SBLK + threadIdx.x;
    int v = (i < N_NODES) ? g_deg[i] : 0;
    __shared__ int ws[8];
    int lane = threadIdx.x & 31, wid = threadIdx.x >> 5;
    int s = v;
#pragma unroll
    for (int off = 16; off; off >>= 1) s += __shfl_xor_sync(0xffffffff, s, off);
    if (lane == 0) ws[wid] = s;
    __syncthreads();
    if (threadIdx.x == 0) {
        int t = 0;
#pragma unroll
        for (int w = 0; w < 8; w++) t += ws[w];
        g_bsum[blockIdx.x] = t;
    }
}

__global__ void scan_bsum_kernel() {
    int t = threadIdx.x;
    int v = (t < NBLOCKS_SCAN) ? g_bsum[t] : 0;
    __shared__ int ws[8];
    int lane = t & 31, wid = t >> 5;
    int inc = warp_incl_scan(v, lane);
    if (lane == 31) ws[wid] = inc;
    __syncthreads();
    if (wid == 0) {
        int wv = (lane < 8) ? ws[lane] : 0;
        int winc = warp_incl_scan(wv, lane);
        if (lane < 8) ws[lane] = winc;
    }
    __syncthreads();
    int excl = inc - v + (wid ? ws[wid - 1] : 0);
    if (t < NBLOCKS_SCAN) g_boff[t] = excl;
    if (t == NBLOCKS_SCAN - 1) g_ptr[N_NODES] = excl + v;
}

__global__ void scan_final_kernel() {
    int i = blockIdx.x * SBLK + threadIdx.x;
    int v = (i < N_NODES) ? g_deg[i] : 0;
    __shared__ int ws[8];
    int lane = threadIdx.x & 31, wid = threadIdx.x >> 5;
    int inc = warp_incl_scan(v, lane);
    if (lane == 31) ws[wid] = inc;
    __syncthreads();
    if (wid == 0) {
        int wv = (lane < 8) ? ws[lane] : 0;
        int winc = warp_incl_scan(wv, lane);
        if (lane < 8) ws[lane] = winc;
    }
    __syncthreads();
    int excl = inc - v + (wid ? ws[wid - 1] : 0) + g_boff[blockIdx.x];
    if (i < N_NODES) { g_ptr[i] = excl; g_work[i] = excl; }
}

__global__ void scatter_kernel(const void* __restrict__ ei) {
    int e = blockIdx.x * blockDim.x + threadIdx.x;
    if (e >= E_TOT) return;
    int s, d; edge_sd(ei, g_e64, e, s, d);
    int pos = atomicAdd(&g_work[d], 1);
    g_src_csr[pos] = s;
}

// ---------------- register-tiled GEMM with fused attention-logit epilogue ----------------
// Tile: 64 rows x NCOL cols per 256-thread block. Thread computes RPT rows x 4 cols.
// TCN thread-cols (tc = tid % TCN), 256/TCN thread-rows of RPT rows each.
// MODE 1: X = x -> g_xl1 (NCOL=128, H=2, TCN=32, RPT=8); writes g_as1/g_ad1.
// MODE 2: X = g_h1 -> g_xl2 (NCOL=64, H=1, TCN=16, RPT=4); writes g_as2/g_ad2.
template<int NCOL, int MODE, int TCN, int RPT>
__global__ void gemm_kernel(const float* __restrict__ Xext,
                            const float* __restrict__ W,
                            const float* __restrict__ att_src,
                            const float* __restrict__ att_dst) {
    extern __shared__ float sm[];
    float* sX = sm;                       // [64][XPITCH]
    float* sW = sm + 64 * XPITCH;         // [128][NCOL]

    const float* X   = (MODE == 1) ? Xext : g_h1;
    float*       out = (MODE == 1) ? g_xl1 : g_xl2;

    const int tid  = threadIdx.x;
    const int row0 = blockIdx.x * 64;
    const int tc   = tid % TCN;
    const int tr   = tid / TCN;

    // stage W [128][NCOL] (row-major, contiguous copy)
    {
        const float4* Wv  = (const float4*)W;
        float4*       sWv = (float4*)sW;
        const int nv = 128 * NCOL / 4;
        for (int i = tid; i < nv; i += 256) sWv[i] = Wv[i];
    }
    // stage X tile (64 rows x 128), zero-padded past N_NODES
    for (int i = tid; i < 64 * 32; i += 256) {
        int r = i >> 5, c4 = i & 31;
        int row = row0 + r;
        float4 v = (row < N_NODES) ? ((const float4*)(X + (size_t)row * 128))[c4]
                                   : make_float4(0.f, 0.f, 0.f, 0.f);
        *(float4*)(sX + r * XPITCH + c4 * 4) = v;
    }
    __syncthreads();

    float acc[RPT][4];
#pragma unroll
    for (int i = 0; i < RPT; i++)
#pragma unroll
        for (int c = 0; c < 4; c++) acc[i][c] = 0.0f;

#pragma unroll 4
    for (int k = 0; k < 128; k++) {
        float4 w4 = *(const float4*)(sW + k * NCOL + tc * 4);
#pragma unroll
        for (int i = 0; i < RPT; i++) {
            float a = sX[(tr * RPT + i) * XPITCH + k];
            acc[i][0] += a * w4.x;
            acc[i][1] += a * w4.y;
            acc[i][2] += a * w4.z;
            acc[i][3] += a * w4.w;
        }
    }

    // epilogue: attention logits (per-row dot with att vectors) + store C
    float4 as4 = ((const float4*)att_src)[tc];
    float4 ad4 = ((const float4*)att_dst)[tc];
#pragma unroll
    for (int i = 0; i < RPT; i++) {
        int row = row0 + tr * RPT + i;
        float ps = acc[i][0] * as4.x + acc[i][1] * as4.y + acc[i][2] * as4.z + acc[i][3] * as4.w;
        float pd = acc[i][0] * ad4.x + acc[i][1] * ad4.y + acc[i][2] * ad4.z + acc[i][3] * ad4.w;
#pragma unroll
        for (int off = 8; off; off >>= 1) {
            ps += __shfl_xor_sync(0xffffffffu, ps, off);
            pd += __shfl_xor_sync(0xffffffffu, pd, off);
        }
        if ((tid & 15) == 0 && row < N_NODES) {
            if (MODE == 1) {
                int h = (tid >> 4) & 1;   // lanes 0-15 = cols 0-63 = head 0; 16-31 = head 1
                g_as1[row * 2 + h] = ps;
                g_ad1[row * 2 + h] = pd;
            } else {
                g_as2[row] = ps;
                g_ad2[row] = pd;
            }
        }
        if (row < N_NODES) {
            float4 o = make_float4(acc[i][0], acc[i][1], acc[i][2], acc[i][3]);
            *(float4*)(out + (size_t)row * NCOL + tc * 4) = o;
        }
    }
}

// ---------------- fused softmax + aggregation (CSR, warp per dst node) ----------------
// Softmax shift dropped (logits O(1), softmax shift-invariant).
__global__ void fused1_kernel(const float* __restrict__ b1) {
    __shared__ int   s_src[8][STAGE];
    __shared__ float s_e  [8][STAGE * 2];
    int node = (blockIdx.x * blockDim.x + threadIdx.x) >> 5;
    int lane = threadIdx.x & 31;
    int wslot = (threadIdx.x >> 5);
    if (node >= N_NODES) return;
    int start = g_ptr[node], end = g_ptr[node + 1];
    int deg = end - start;
    bool sm = (deg <= STAGE);

    float ad0 = g_ad1[node * 2 + 0];
    float ad1 = g_ad1[node * 2 + 1];

    float den0 = 0.0f, den1 = 0.0f;
    for (int j = start + lane; j < end; j += 32) {
        int s = g_src_csr[j];
        float2 as = ((const float2*)g_as1)[s];
        float e0 = expf(lrelu(as.x + ad0));
        float e1 = expf(lrelu(as.y + ad1));
        if (sm) {
            int k = j - start;
            s_src[wslot][k] = s;
            s_e[wslot][k * 2 + 0] = e0;
            s_e[wslot][k * 2 + 1] = e1;
        } else {
            ((float2*)g_e_csr)[j] = make_float2(e0, e1);
        }
        den0 += e0; den1 += e1;
    }
#pragma unroll
    for (int off = 16; off; off >>= 1) {
        den0 += __shfl_xor_sync(0xffffffff, den0, off);
        den1 += __shfl_xor_sync(0xffffffff, den1, off);
    }
    int h = lane >> 4;
    float rden = 1.0f / (h ? den1 : den0);
    __syncwarp();

    float4 bv = ((const float4*)b1)[lane];
    float a0 = bv.x, a1 = bv.y, a2 = bv.z, a3 = bv.w;
    if (sm) {
#pragma unroll 4
        for (int k = 0; k < deg; k++) {
            int s = s_src[wslot][k];
            float alpha = s_e[wslot][k * 2 + h] * rden;
            float4 xv = ((const float4*)(g_xl1 + (size_t)s * 128))[lane];
            a0 += alpha * xv.x; a1 += alpha * xv.y;
            a2 += alpha * xv.z; a3 += alpha * xv.w;
        }
    } else {
        for (int j = start; j < end; j++) {
            int s = g_src_csr[j];
            float alpha = g_e_csr[j * 2 + h] * rden;
            float4 xv = ((const float4*)(g_xl1 + (size_t)s * 128))[lane];
            a0 += alpha * xv.x; a1 += alpha * xv.y;
            a2 += alpha * xv.z; a3 += alpha * xv.w;
        }
    }
    float4 r = make_float4(fmaxf(a0, 0.f), fmaxf(a1, 0.f), fmaxf(a2, 0.f), fmaxf(a3, 0.f));
    ((float4*)(g_h1 + (size_t)node * 128))[lane] = r;
}

__global__ void fused2_kernel(const float* __restrict__ b2, float* __restrict__ out) {
    __shared__ int   s_src[8][STAGE];
    __shared__ float s_e  [8][STAGE];
    int node = (blockIdx.x * blockDim.x + threadIdx.x) >> 5;
    int lane = threadIdx.x & 31;
    int wslot = (threadIdx.x >> 5);
    if (node >= N_NODES) return;
    int start = g_ptr[node], end = g_ptr[node + 1];
    int deg = end - start;
    bool sm = (deg <= STAGE);

    float adv = g_ad2[node];

    float den = 0.0f;
    for (int j = start + lane; j < end; j += 32) {
        int s = g_src_csr[j];
        float ev = expf(lrelu(g_as2[s] + adv));
        if (sm) {
            int k = j - start;
            s_src[wslot][k] = s;
            s_e[wslot][k] = ev;
        } else {
            g_e_csr[j] = ev;
        }
        den += ev;
    }
#pragma unroll
    for (int off = 16; off; off >>= 1)
        den += __shfl_xor_sync(0xffffffff, den, off);
    float rden = 1.0f / den;
    __syncwarp();

    float2 bv = ((const float2*)b2)[lane];
    float a0 = bv.x, a1 = bv.y;
    if (sm) {
#pragma unroll 4
        for (int k = 0; k < deg; k++) {
            int s = s_src[wslot][k];
            float alpha = s_e[wslot][k] * rden;
            float2 xv = ((const float2*)(g_xl2 + (size_t)s * 64))[lane];
            a0 += alpha * xv.x; a1 += alpha * xv.y;
        }
    } else {
        for (int j = start; j < end; j++) {
            int s = g_src_csr[j];
            float alpha = g_e_csr[j] * rden;
            float2 xv = ((const float2*)(g_xl2 + (size_t)s * 64))[lane];
            a0 += alpha * xv.x; a1 += alpha * xv.y;
        }
    }
    float2 r = make_float2(fmaxf(a0, 0.f), fmaxf(a1, 0.f));
    ((float2*)(out + (size_t)node * 64))[lane] = r;
}

// ---------------- launch ----------------
extern "C" void kernel_launch(void* const* d_in, const int* in_sizes, int n_in,
                              void* d_out, int out_size) {
    const float *x = 0, *W1 = 0, *W2 = 0;
    const void  *ei = 0;
    const float *v128[3] = {0, 0, 0};
    const float *v64 [3] = {0, 0, 0};
    int n128 = 0, n64 = 0;
    for (int i = 0; i < n_in; i++) {
        int sz = in_sizes[i];
        if      (sz == N_NODES * 128) x  = (const float*)d_in[i];
        else if (sz == 2 * N_EDGES)   ei = d_in[i];
        else if (sz == 128 * 128)     W1 = (const float*)d_in[i];
        else if (sz == 128 * 64)      W2 = (const float*)d_in[i];
        else if (sz == 128 && n128 < 3) v128[n128++] = (const float*)d_in[i];
        else if (sz == 64  && n64  < 3) v64 [n64++]  = (const float*)d_in[i];
    }
    const float* att_src1 = v128[0];
    const float* att_dst1 = v128[1];
    const float* b1       = v128[2];
    const float* att_src2 = v64[0];
    const float* att_dst2 = v64[1];
    const float* b2       = v64[2];
    float* out = (float*)d_out;

    const int TPB = 256;
    const int edge_blocks = (E_TOT + TPB - 1) / TPB;
    const int warp_blocks = (N_NODES * 32 + TPB - 1) / TPB;
    const int gemm_blocks = (N_NODES + 63) / 64;               // 782
    const int prep_blocks = (N_NODES + TPB - 1) / TPB;

    const int smem1 = (64 * XPITCH + 128 * 128) * 4;           // 99,328 B
    const int smem2 = (64 * XPITCH + 128 * 64) * 4;            // 66,560 B
    cudaFuncSetAttribute(gemm_kernel<128, 1, 32, 8>,
                         cudaFuncAttributeMaxDynamicSharedMemorySize, smem1);
    cudaFuncSetAttribute(gemm_kernel<64, 2, 16, 4>,
                         cudaFuncAttributeMaxDynamicSharedMemorySize, smem2);

    // CSR by destination
    prep_kernel<<<prep_blocks, TPB>>>((const long long*)ei);
    hist_kernel<<<edge_blocks, TPB>>>(ei);
    scan_partial_kernel<<<NBLOCKS_SCAN, SBLK>>>();
    scan_bsum_kernel<<<1, 256>>>();
    scan_final_kernel<<<NBLOCKS_SCAN, SBLK>>>();
    scatter_kernel<<<edge_blocks, TPB>>>(ei);

    // Layer 1
    gemm_kernel<128, 1, 32, 8><<<gemm_blocks, TPB, smem1>>>(x, W1, att_src1, att_dst1);
    fused1_kernel<<<warp_blocks, TPB>>>(b1);

    // Layer 2
    gemm_kernel<64, 2, 16, 4><<<gemm_blocks, TPB, smem2>>>(x, W2, att_src2, att_dst2);
    fused2_kernel<<<warp_blocks, TPB>>>(b2, out);
}

// round 9
// speedup vs baseline: 1.6655x; 1.0924x over previous
#include <cuda_runtime.h>
#include <cuda_fp16.h>
#include <math.h>
#include <stdint.h>

#define N_NODES 50000
#define N_EDGES 1600000
#define E_TOT   1650000   // + self loops
#define NEG_SLOPE 0.2f

#define SBLK 256
#define NBLOCKS_SCAN ((N_NODES + SBLK - 1) / SBLK)   // 196
#define STAGE 128        // per-warp smem staging capacity (deg is Poisson(33))
#define XPITCH 132       // padded smem row pitch (16B-aligned, bank-shifted)

// ---------------- scratch (device globals; only referenced from device code) ----------------
__device__ __align__(16) __half2 g_xl1h[N_NODES * 64];  // layer1 feats, fp16 [N,128]
__device__ __align__(16) __half2 g_xl2h[N_NODES * 32];  // layer2 feats, fp16 [N,64]
__device__ __align__(16) float   g_h1 [N_NODES * 128];  // relu(layer1 out), fp32
__device__ __align__(16) float   g_as1[N_NODES * 2];
__device__ __align__(16) float   g_ad1[N_NODES * 2];
__device__ __align__(16) float   g_as2[N_NODES];
__device__ __align__(16) float   g_ad2[N_NODES];

__device__ __align__(16) int   g_deg [N_NODES];
__device__ __align__(16) int   g_ptr [N_NODES + 1];
__device__ __align__(16) int   g_work[N_NODES];
__device__ __align__(16) int   g_src_csr[E_TOT];
__device__ __align__(16) float g_e_csr[E_TOT * 2];   // fallback only (deg > STAGE)
__device__ __align__(16) int   g_bsum[NBLOCKS_SCAN];

__device__ int g_e64;

// ---------------- helpers ----------------
__device__ __forceinline__ float lrelu(float x) {
    return x >= 0.0f ? x : NEG_SLOPE * x;
}

__device__ __forceinline__ void edge_sd(const void* ei, int is64, int e, int& s, int& d) {
    if (e >= N_EDGES) { s = d = e - N_EDGES; return; }
    if (is64) {
        const long long* p = (const long long*)ei;
        s = (int)p[e];
        d = (int)p[N_EDGES + e];
    } else {
        const int* p = (const int*)ei;
        s = p[e];
        d = p[N_EDGES + e];
    }
}

__device__ __forceinline__ int warp_incl_scan(int v, int lane) {
#pragma unroll
    for (int off = 1; off < 32; off <<= 1) {
        int n = __shfl_up_sync(0xffffffff, v, off);
        if (lane >= off) v += n;
    }
    return v;
}

// ---------------- graph preprocessing ----------------
__global__ void prep_kernel(const long long* ei) {
    int i = blockIdx.x * blockDim.x + threadIdx.x;
    if (i < N_NODES) g_deg[i] = 0;
    if (blockIdx.x == 0) {
        __shared__ int bad;
        if (threadIdx.x == 0) bad = 0;
        __syncthreads();
        long long v = ei[threadIdx.x];
        if (v < 0 || v >= N_NODES) bad = 1;
        __syncthreads();
        if (threadIdx.x == 0) g_e64 = bad ? 0 : 1;
    }
}

__global__ void hist_kernel(const void* __restrict__ ei) {
    int e = blockIdx.x * blockDim.x + threadIdx.x;
    if (e >= E_TOT) return;
    int s, d; edge_sd(ei, g_e64, e, s, d);
    atomicAdd(&g_deg[d], 1);
}

__global__ void scan_partial_kernel() {
    int i = blockIdx.x * SBLK + threadIdx.x;
    int v = (i < N_NODES) ? g_deg[i] : 0;
    __shared__ int ws[8];
    int lane = threadIdx.x & 31, wid = threadIdx.x >> 5;
    int s = v;
#pragma unroll
    for (int off = 16; off; off >>= 1) s += __shfl_xor_sync(0xffffffff, s, off);
    if (lane == 0) ws[wid] = s;
    __syncthreads();
    if (threadIdx.x == 0) {
        int t = 0;
#pragma unroll
        for (int w = 0; w < 8; w++) t += ws[w];
        g_bsum[blockIdx.x] = t;
    }
}

// Final scan: every block redundantly scans the 196 block sums in smem,
// then produces its 256 per-node exclusive prefixes (1 launch instead of 2).
__global__ void scan_final_kernel() {
    __shared__ int s_boff[NBLOCKS_SCAN];
    __shared__ int ws2[8];
    __shared__ int ws[8];
    int t = threadIdx.x;
    int lane = t & 31, wid = t >> 5;

    // block-sum exclusive scan (redundant per block; 196 values)
    {
        int v = (t < NBLOCKS_SCAN) ? g_bsum[t] : 0;
        int inc = warp_incl_scan(v, lane);
        if (lane == 31) ws2[wid] = inc;
        __syncthreads();
        if (wid == 0) {
            int wv = (lane < 8) ? ws2[lane] : 0;
            int winc = warp_incl_scan(wv, lane);
            if (lane < 8) ws2[lane] = winc;
        }
        __syncthreads();
        int excl = inc - v + (wid ? ws2[wid - 1] : 0);
        if (t < NBLOCKS_SCAN) s_boff[t] = excl;
        if (blockIdx.x == 0 && t == NBLOCKS_SCAN - 1) g_ptr[N_NODES] = excl + v;
    }
    __syncthreads();

    // per-node exclusive scan within this block
    int i = blockIdx.x * SBLK + t;
    int v = (i < N_NODES) ? g_deg[i] : 0;
    int inc = warp_incl_scan(v, lane);
    if (lane == 31) ws[wid] = inc;
    __syncthreads();
    if (wid == 0) {
        int wv = (lane < 8) ? ws[lane] : 0;
        int winc = warp_incl_scan(wv, lane);
        if (lane < 8) ws[lane] = winc;
    }
    __syncthreads();
    int excl = inc - v + (wid ? ws[wid - 1] : 0) + s_boff[blockIdx.x];
    if (i < N_NODES) { g_ptr[i] = excl; g_work[i] = excl; }
}

__global__ void scatter_kernel(const void* __restrict__ ei) {
    int e = blockIdx.x * blockDim.x + threadIdx.x;
    if (e >= E_TOT) return;
    int s, d; edge_sd(ei, g_e64, e, s, d);
    int pos = atomicAdd(&g_work[d], 1);
    g_src_csr[pos] = s;
}

// ---------------- register-tiled GEMM, fp16 output + fused attention logits ----------------
// Tile: 64 rows x NCOL cols per 256-thread block. Thread computes RPT rows x 4 cols.
// MODE 1: X = x    -> g_xl1h (NCOL=128, TCN=32, RPT=8); logits -> g_as1/g_ad1 (H=2).
// MODE 2: X = g_h1 -> g_xl2h (NCOL=64,  TCN=16, RPT=4); logits -> g_as2/g_ad2 (H=1).
template<int NCOL, int MODE, int TCN, int RPT>
__global__ void gemm_kernel(const float* __restrict__ Xext,
                            const float* __restrict__ W,
                            const float* __restrict__ att_src,
                            const float* __restrict__ att_dst) {
    extern __shared__ float sm[];
    float* sX = sm;                       // [64][XPITCH]
    float* sW = sm + 64 * XPITCH;         // [128][NCOL]

    const float* X = (MODE == 1) ? Xext : g_h1;
    __half2*     out = (MODE == 1) ? g_xl1h : g_xl2h;
    constexpr int OUTP = NCOL / 2;        // half2 row pitch

    const int tid  = threadIdx.x;
    const int row0 = blockIdx.x * 64;
    const int tc   = tid % TCN;
    const int tr   = tid / TCN;

    {
        const float4* Wv  = (const float4*)W;
        float4*       sWv = (float4*)sW;
        const int nv = 128 * NCOL / 4;
        for (int i = tid; i < nv; i += 256) sWv[i] = Wv[i];
    }
    for (int i = tid; i < 64 * 32; i += 256) {
        int r = i >> 5, c4 = i & 31;
        int row = row0 + r;
        float4 v = (row < N_NODES) ? ((const float4*)(X + (size_t)row * 128))[c4]
                                   : make_float4(0.f, 0.f, 0.f, 0.f);
        *(float4*)(sX + r * XPITCH + c4 * 4) = v;
    }
    __syncthreads();

    float acc[RPT][4];
#pragma unroll
    for (int i = 0; i < RPT; i++)
#pragma unroll
        for (int c = 0; c < 4; c++) acc[i][c] = 0.0f;

#pragma unroll 4
    for (int k = 0; k < 128; k++) {
        float4 w4 = *(const float4*)(sW + k * NCOL + tc * 4);
#pragma unroll
        for (int i = 0; i < RPT; i++) {
            float a = sX[(tr * RPT + i) * XPITCH + k];
            acc[i][0] += a * w4.x;
            acc[i][1] += a * w4.y;
            acc[i][2] += a * w4.z;
            acc[i][3] += a * w4.w;
        }
    }

    float4 as4 = ((const float4*)att_src)[tc];
    float4 ad4 = ((const float4*)att_dst)[tc];
#pragma unroll
    for (int i = 0; i < RPT; i++) {
        int row = row0 + tr * RPT + i;
        float ps = acc[i][0] * as4.x + acc[i][1] * as4.y + acc[i][2] * as4.z + acc[i][3] * as4.w;
        float pd = acc[i][0] * ad4.x + acc[i][1] * ad4.y + acc[i][2] * ad4.z + acc[i][3] * ad4.w;
#pragma unroll
        for (int off = 8; off; off >>= 1) {
            ps += __shfl_xor_sync(0xffffffffu, ps, off);
            pd += __shfl_xor_sync(0xffffffffu, pd, off);
        }
        if ((tid & 15) == 0 && row < N_NODES) {
            if (MODE == 1) {
                int h = (tid >> 4) & 1;
                g_as1[row * 2 + h] = ps;
                g_ad1[row * 2 + h] = pd;
            } else {
                g_as2[row] = ps;
                g_ad2[row] = pd;
            }
        }
        if (row < N_NODES) {
            __half2 h0 = __floats2half2_rn(acc[i][0], acc[i][1]);
            __half2 h1 = __floats2half2_rn(acc[i][2], acc[i][3]);
            uint2 pk = make_uint2(*(unsigned*)&h0, *(unsigned*)&h1);
            *(uint2*)(out + (size_t)row * OUTP + tc * 2) = pk;   // 8B store
        }
    }
}

// ---------------- fused softmax + aggregation (CSR, warp per dst node, fp16 gather) ----------------
// Softmax shift dropped (logits O(1), softmax shift-invariant).
__global__ void fused1_kernel(const float* __restrict__ b1) {
    __shared__ int   s_src[8][STAGE];
    __shared__ float s_e  [8][STAGE * 2];
    int node = (blockIdx.x * blockDim.x + threadIdx.x) >> 5;
    int lane = threadIdx.x & 31;
    int wslot = (threadIdx.x >> 5);
    if (node >= N_NODES) return;
    int start = g_ptr[node], end = g_ptr[node + 1];
    int deg = end - start;
    bool sm = (deg <= STAGE);

    float ad0 = g_ad1[node * 2 + 0];
    float ad1 = g_ad1[node * 2 + 1];

    float den0 = 0.0f, den1 = 0.0f;
    for (int j = start + lane; j < end; j += 32) {
        int s = g_src_csr[j];
        float2 as = ((const float2*)g_as1)[s];
        float e0 = expf(lrelu(as.x + ad0));
        float e1 = expf(lrelu(as.y + ad1));
        if (sm) {
            int k = j - start;
            s_src[wslot][k] = s;
            s_e[wslot][k * 2 + 0] = e0;
            s_e[wslot][k * 2 + 1] = e1;
        } else {
            ((float2*)g_e_csr)[j] = make_float2(e0, e1);
        }
        den0 += e0; den1 += e1;
    }
#pragma unroll
    for (int off = 16; off; off >>= 1) {
        den0 += __shfl_xor_sync(0xffffffff, den0, off);
        den1 += __shfl_xor_sync(0xffffffff, den1, off);
    }
    int h = lane >> 4;
    float rden = 1.0f / (h ? den1 : den0);
    __syncwarp();

    float4 bv = ((const float4*)b1)[lane];
    float a0 = bv.x, a1 = bv.y, a2 = bv.z, a3 = bv.w;
    if (sm) {
#pragma unroll 4
        for (int k = 0; k < deg; k++) {
            int s = s_src[wslot][k];
            float alpha = s_e[wslot][k * 2 + h] * rden;
            uint2 pk = *(const uint2*)(g_xl1h + (size_t)s * 64 + lane * 2);
            float2 f0 = __half22float2(*(__half2*)&pk.x);
            float2 f1 = __half22float2(*(__half2*)&pk.y);
            a0 += alpha * f0.x; a1 += alpha * f0.y;
            a2 += alpha * f1.x; a3 += alpha * f1.y;
        }
    } else {
        for (int j = start; j < end; j++) {
            int s = g_src_csr[j];
            float alpha = g_e_csr[j * 2 + h] * rden;
            uint2 pk = *(const uint2*)(g_xl1h + (size_t)s * 64 + lane * 2);
            float2 f0 = __half22float2(*(__half2*)&pk.x);
            float2 f1 = __half22float2(*(__half2*)&pk.y);
            a0 += alpha * f0.x; a1 += alpha * f0.y;
            a2 += alpha * f1.x; a3 += alpha * f1.y;
        }
    }
    float4 r = make_float4(fmaxf(a0, 0.f), fmaxf(a1, 0.f), fmaxf(a2, 0.f), fmaxf(a3, 0.f));
    ((float4*)(g_h1 + (size_t)node * 128))[lane] = r;
}

__global__ void fused2_kernel(const float* __restrict__ b2, float* __restrict__ out) {
    __shared__ int   s_src[8][STAGE];
    __shared__ float s_e  [8][STAGE];
    int node = (blockIdx.x * blockDim.x + threadIdx.x) >> 5;
    int lane = threadIdx.x & 31;
    int wslot = (threadIdx.x >> 5);
    if (node >= N_NODES) return;
    int start = g_ptr[node], end = g_ptr[node + 1];
    int deg = end - start;
    bool sm = (deg <= STAGE);

    float adv = g_ad2[node];

    float den = 0.0f;
    for (int j = start + lane; j < end; j += 32) {
        int s = g_src_csr[j];
        float ev = expf(lrelu(g_as2[s] + adv));
        if (sm) {
            int k = j - start;
            s_src[wslot][k] = s;
            s_e[wslot][k] = ev;
        } else {
            g_e_csr[j] = ev;
        }
        den += ev;
    }
#pragma unroll
    for (int off = 16; off; off >>= 1)
        den += __shfl_xor_sync(0xffffffff, den, off);
    float rden = 1.0f / den;
    __syncwarp();

    float2 bv = ((const float2*)b2)[lane];
    float a0 = bv.x, a1 = bv.y;
    if (sm) {
#pragma unroll 4
        for (int k = 0; k < deg; k++) {
            int s = s_src[wslot][k];
            float alpha = s_e[wslot][k] * rden;
            float2 f = __half22float2(g_xl2h[(size_t)s * 32 + lane]);
            a0 += alpha * f.x; a1 += alpha * f.y;
        }
    } else {
        for (int j = start; j < end; j++) {
            int s = g_src_csr[j];
            float alpha = g_e_csr[j] * rden;
            float2 f = __half22float2(g_xl2h[(size_t)s * 32 + lane]);
            a0 += alpha * f.x; a1 += alpha * f.y;
        }
    }
    float2 r = make_float2(fmaxf(a0, 0.f), fmaxf(a1, 0.f));
    ((float2*)(out + (size_t)node * 64))[lane] = r;
}

// ---------------- launch ----------------
extern "C" void kernel_launch(void* const* d_in, const int* in_sizes, int n_in,
                              void* d_out, int out_size) {
    const float *x = 0, *W1 = 0, *W2 = 0;
    const void  *ei = 0;
    const float *v128[3] = {0, 0, 0};
    const float *v64 [3] = {0, 0, 0};
    int n128 = 0, n64 = 0;
    for (int i = 0; i < n_in; i++) {
        int sz = in_sizes[i];
        if      (sz == N_NODES * 128) x  = (const float*)d_in[i];
        else if (sz == 2 * N_EDGES)   ei = d_in[i];
        else if (sz == 128 * 128)     W1 = (const float*)d_in[i];
        else if (sz == 128 * 64)      W2 = (const float*)d_in[i];
        else if (sz == 128 && n128 < 3) v128[n128++] = (const float*)d_in[i];
        else if (sz == 64  && n64  < 3) v64 [n64++]  = (const float*)d_in[i];
    }
    const float* att_src1 = v128[0];
    const float* att_dst1 = v128[1];
    const float* b1       = v128[2];
    const float* att_src2 = v64[0];
    const float* att_dst2 = v64[1];
    const float* b2       = v64[2];
    float* out = (float*)d_out;

    const int TPB = 256;
    const int edge_blocks = (E_TOT + TPB - 1) / TPB;
    const int warp_blocks = (N_NODES * 32 + TPB - 1) / TPB;
    const int gemm_blocks = (N_NODES + 63) / 64;
    const int prep_blocks = (N_NODES + TPB - 1) / TPB;

    const int smem1 = (64 * XPITCH + 128 * 128) * 4;           // 99,328 B
    const int smem2 = (64 * XPITCH + 128 * 64) * 4;            // 66,560 B
    cudaFuncSetAttribute(gemm_kernel<128, 1, 32, 8>,
                         cudaFuncAttributeMaxDynamicSharedMemorySize, smem1);
    cudaFuncSetAttribute(gemm_kernel<64, 2, 16, 4>,
                         cudaFuncAttributeMaxDynamicSharedMemorySize, smem2);

    // CSR by destination
    prep_kernel<<<prep_blocks, TPB>>>((const long long*)ei);
    hist_kernel<<<edge_blocks, TPB>>>(ei);
    scan_partial_kernel<<<NBLOCKS_SCAN, SBLK>>>();
    scan_final_kernel<<<NBLOCKS_SCAN, SBLK>>>();
    scatter_kernel<<<edge_blocks, TPB>>>(ei);

    // Layer 1
    gemm_kernel<128, 1, 32, 8><<<gemm_blocks, TPB, smem1>>>(x, W1, att_src1, att_dst1);
    fused1_kernel<<<warp_blocks, TPB>>>(b1);

    // Layer 2
    gemm_kernel<64, 2, 16, 4><<<gemm_blocks, TPB, smem2>>>(x, W2, att_src2, att_dst2);
    fused2_kernel<<<warp_blocks, TPB>>>(b2, out);
}

// round 10
// speedup vs baseline: 1.8129x; 1.0885x over previous
#include <cuda_runtime.h>
#include <cuda_fp16.h>
#include <math.h>
#include <stdint.h>

#define N_NODES 50000
#define N_EDGES 1600000
#define E_TOT   1650000   // + self loops
#define NEG_SLOPE 0.2f

#define SBLK 256
#define NBLOCKS_SCAN ((N_NODES + SBLK - 1) / SBLK)   // 196
#define STAGE 128        // per-warp smem staging capacity (deg is Poisson(33))
#define XPITCH 132       // padded smem row pitch (16B-aligned, bank-shifted)

// ---------------- scratch (device globals; only referenced from device code) ----------------
__device__ __align__(16) __half2 g_xl1h[N_NODES * 64];  // layer1 feats, fp16 [N,128]
__device__ __align__(16) __half2 g_xl2h[N_NODES * 32];  // layer2 feats, fp16 [N,64]
__device__ __align__(16) float   g_h1 [N_NODES * 128];  // relu(layer1 out), fp32
__device__ __align__(16) float   g_as1[N_NODES * 2];
__device__ __align__(16) float   g_ad1[N_NODES * 2];
__device__ __align__(16) float   g_as2[N_NODES];
__device__ __align__(16) float   g_ad2[N_NODES];

__device__ __align__(16) int   g_deg [N_NODES];
__device__ __align__(16) int   g_ptr [N_NODES + 1];
__device__ __align__(16) int   g_work[N_NODES];
__device__ __align__(16) int   g_src_csr[E_TOT];
__device__ __align__(16) float g_e_csr[E_TOT * 2];   // fallback only (deg > STAGE)
__device__ __align__(16) int   g_bsum[NBLOCKS_SCAN];

__device__ int g_e64;

// ---------------- helpers ----------------
__device__ __forceinline__ float lrelu(float x) {
    return x >= 0.0f ? x : NEG_SLOPE * x;
}

__device__ __forceinline__ void edge_sd(const void* ei, int is64, int e, int& s, int& d) {
    if (e >= N_EDGES) { s = d = e - N_EDGES; return; }
    if (is64) {
        const long long* p = (const long long*)ei;
        s = (int)p[e];
        d = (int)p[N_EDGES + e];
    } else {
        const int* p = (const int*)ei;
        s = p[e];
        d = p[N_EDGES + e];
    }
}

__device__ __forceinline__ int warp_incl_scan(int v, int lane) {
#pragma unroll
    for (int off = 1; off < 32; off <<= 1) {
        int n = __shfl_up_sync(0xffffffff, v, off);
        if (lane >= off) v += n;
    }
    return v;
}

// ---------------- graph preprocessing ----------------
__global__ void prep_kernel(const long long* ei) {
    int i = blockIdx.x * blockDim.x + threadIdx.x;
    if (i < N_NODES) g_deg[i] = 0;
    if (blockIdx.x == 0) {
        __shared__ int bad;
        if (threadIdx.x == 0) bad = 0;
        __syncthreads();
        long long v = ei[threadIdx.x];
        if (v < 0 || v >= N_NODES) bad = 1;
        __syncthreads();
        if (threadIdx.x == 0) g_e64 = bad ? 0 : 1;
    }
}

__global__ void hist_kernel(const void* __restrict__ ei) {
    int e = blockIdx.x * blockDim.x + threadIdx.x;
    if (e >= E_TOT) return;
    int s, d; edge_sd(ei, g_e64, e, s, d);
    atomicAdd(&g_deg[d], 1);
}

__global__ void scan_partial_kernel() {
    int i = blockIdx.x * SBLK + threadIdx.x;
    int v = (i < N_NODES) ? g_deg[i] : 0;
    __shared__ int ws[8];
    int lane = threadIdx.x & 31, wid = threadIdx.x >> 5;
    int s = v;
#pragma unroll
    for (int off = 16; off; off >>= 1) s += __shfl_xor_sync(0xffffffff, s, off);
    if (lane == 0) ws[wid] = s;
    __syncthreads();
    if (threadIdx.x == 0) {
        int t = 0;
#pragma unroll
        for (int w = 0; w < 8; w++) t += ws[w];
        g_bsum[blockIdx.x] = t;
    }
}

// Final scan: every block redundantly scans the 196 block sums in smem,
// then produces its 256 per-node exclusive prefixes.
__global__ void scan_final_kernel() {
    __shared__ int s_boff[NBLOCKS_SCAN];
    __shared__ int ws2[8];
    __shared__ int ws[8];
    int t = threadIdx.x;
    int lane = t & 31, wid = t >> 5;

    {
        int v = (t < NBLOCKS_SCAN) ? g_bsum[t] : 0;
        int inc = warp_incl_scan(v, lane);
        if (lane == 31) ws2[wid] = inc;
        __syncthreads();
        if (wid == 0) {
            int wv = (lane < 8) ? ws2[lane] : 0;
            int winc = warp_incl_scan(wv, lane);
            if (lane < 8) ws2[lane] = winc;
        }
        __syncthreads();
        int excl = inc - v + (wid ? ws2[wid - 1] : 0);
        if (t < NBLOCKS_SCAN) s_boff[t] = excl;
        if (blockIdx.x == 0 && t == NBLOCKS_SCAN - 1) g_ptr[N_NODES] = excl + v;
    }
    __syncthreads();

    int i = blockIdx.x * SBLK + t;
    int v = (i < N_NODES) ? g_deg[i] : 0;
    int inc = warp_incl_scan(v, lane);
    if (lane == 31) ws[wid] = inc;
    __syncthreads();
    if (wid == 0) {
        int wv = (lane < 8) ? ws[lane] : 0;
        int winc = warp_incl_scan(wv, lane);
        if (lane < 8) ws[lane] = winc;
    }
    __syncthreads();
    int excl = inc - v + (wid ? ws[wid - 1] : 0) + s_boff[blockIdx.x];
    if (i < N_NODES) { g_ptr[i] = excl; g_work[i] = excl; }
}

__global__ void scatter_kernel(const void* __restrict__ ei) {
    int e = blockIdx.x * blockDim.x + threadIdx.x;
    if (e >= E_TOT) return;
    int s, d; edge_sd(ei, g_e64, e, s, d);
    int pos = atomicAdd(&g_work[d], 1);
    g_src_csr[pos] = s;
}

// ---------------- register-tiled GEMM, fp16 output + fused attention logits ----------------
template<int NCOL, int MODE, int TCN, int RPT>
__global__ void gemm_kernel(const float* __restrict__ Xext,
                            const float* __restrict__ W,
                            const float* __restrict__ att_src,
                            const float* __restrict__ att_dst) {
    extern __shared__ float sm[];
    float* sX = sm;                       // [64][XPITCH]
    float* sW = sm + 64 * XPITCH;         // [128][NCOL]

    const float* X = (MODE == 1) ? Xext : g_h1;
    __half2*     out = (MODE == 1) ? g_xl1h : g_xl2h;
    constexpr int OUTP = NCOL / 2;        // half2 row pitch

    const int tid  = threadIdx.x;
    const int row0 = blockIdx.x * 64;
    const int tc   = tid % TCN;
    const int tr   = tid / TCN;

    {
        const float4* Wv  = (const float4*)W;
        float4*       sWv = (float4*)sW;
        const int nv = 128 * NCOL / 4;
        for (int i = tid; i < nv; i += 256) sWv[i] = Wv[i];
    }
    for (int i = tid; i < 64 * 32; i += 256) {
        int r = i >> 5, c4 = i & 31;
        int row = row0 + r;
        float4 v = (row < N_NODES) ? ((const float4*)(X + (size_t)row * 128))[c4]
                                   : make_float4(0.f, 0.f, 0.f, 0.f);
        *(float4*)(sX + r * XPITCH + c4 * 4) = v;
    }
    __syncthreads();

    float acc[RPT][4];
#pragma unroll
    for (int i = 0; i < RPT; i++)
#pragma unroll
        for (int c = 0; c < 4; c++) acc[i][c] = 0.0f;

#pragma unroll 4
    for (int k = 0; k < 128; k++) {
        float4 w4 = *(const float4*)(sW + k * NCOL + tc * 4);
#pragma unroll
        for (int i = 0; i < RPT; i++) {
            float a = sX[(tr * RPT + i) * XPITCH + k];
            acc[i][0] += a * w4.x;
            acc[i][1] += a * w4.y;
            acc[i][2] += a * w4.z;
            acc[i][3] += a * w4.w;
        }
    }

    float4 as4 = ((const float4*)att_src)[tc];
    float4 ad4 = ((const float4*)att_dst)[tc];
#pragma unroll
    for (int i = 0; i < RPT; i++) {
        int row = row0 + tr * RPT + i;
        float ps = acc[i][0] * as4.x + acc[i][1] * as4.y + acc[i][2] * as4.z + acc[i][3] * as4.w;
        float pd = acc[i][0] * ad4.x + acc[i][1] * ad4.y + acc[i][2] * ad4.z + acc[i][3] * ad4.w;
#pragma unroll
        for (int off = 8; off; off >>= 1) {
            ps += __shfl_xor_sync(0xffffffffu, ps, off);
            pd += __shfl_xor_sync(0xffffffffu, pd, off);
        }
        if ((tid & 15) == 0 && row < N_NODES) {
            if (MODE == 1) {
                int h = (tid >> 4) & 1;
                g_as1[row * 2 + h] = ps;
                g_ad1[row * 2 + h] = pd;
            } else {
                g_as2[row] = ps;
                g_ad2[row] = pd;
            }
        }
        if (row < N_NODES) {
            __half2 h0 = __floats2half2_rn(acc[i][0], acc[i][1]);
            __half2 h1 = __floats2half2_rn(acc[i][2], acc[i][3]);
            uint2 pk = make_uint2(*(unsigned*)&h0, *(unsigned*)&h1);
            *(uint2*)(out + (size_t)row * OUTP + tc * 2) = pk;   // 8B store
        }
    }
}

// ---------------- fused softmax + aggregation (CSR, warp per dst node, fp16 gather) ----------------
__global__ void fused1_kernel(const float* __restrict__ b1) {
    __shared__ int   s_src[8][STAGE];
    __shared__ float s_e  [8][STAGE * 2];
    int node = (blockIdx.x * blockDim.x + threadIdx.x) >> 5;
    int lane = threadIdx.x & 31;
    int wslot = (threadIdx.x >> 5);
    if (node >= N_NODES) return;
    int start = g_ptr[node], end = g_ptr[node + 1];
    int deg = end - start;
    bool sm = (deg <= STAGE);

    float ad0 = g_ad1[node * 2 + 0];
    float ad1 = g_ad1[node * 2 + 1];

    float den0 = 0.0f, den1 = 0.0f;
    for (int j = start + lane; j < end; j += 32) {
        int s = g_src_csr[j];
        float2 as = ((const float2*)g_as1)[s];
        float e0 = expf(lrelu(as.x + ad0));
        float e1 = expf(lrelu(as.y + ad1));
        if (sm) {
            int k = j - start;
            s_src[wslot][k] = s;
            s_e[wslot][k * 2 + 0] = e0;
            s_e[wslot][k * 2 + 1] = e1;
        } else {
            ((float2*)g_e_csr)[j] = make_float2(e0, e1);
        }
        den0 += e0; den1 += e1;
    }
#pragma unroll
    for (int off = 16; off; off >>= 1) {
        den0 += __shfl_xor_sync(0xffffffff, den0, off);
        den1 += __shfl_xor_sync(0xffffffff, den1, off);
    }
    int h = lane >> 4;
    float rden = 1.0f / (h ? den1 : den0);
    __syncwarp();

    float4 bv = ((const float4*)b1)[lane];
    float a0 = bv.x, a1 = bv.y, a2 = bv.z, a3 = bv.w;
    if (sm) {
#pragma unroll 4
        for (int k = 0; k < deg; k++) {
            int s = s_src[wslot][k];
            float alpha = s_e[wslot][k * 2 + h] * rden;
            uint2 pk = *(const uint2*)(g_xl1h + (size_t)s * 64 + lane * 2);
            float2 f0 = __half22float2(*(__half2*)&pk.x);
            float2 f1 = __half22float2(*(__half2*)&pk.y);
            a0 += alpha * f0.x; a1 += alpha * f0.y;
            a2 += alpha * f1.x; a3 += alpha * f1.y;
        }
    } else {
        for (int j = start; j < end; j++) {
            int s = g_src_csr[j];
            float alpha = g_e_csr[j * 2 + h] * rden;
            uint2 pk = *(const uint2*)(g_xl1h + (size_t)s * 64 + lane * 2);
            float2 f0 = __half22float2(*(__half2*)&pk.x);
            float2 f1 = __half22float2(*(__half2*)&pk.y);
            a0 += alpha * f0.x; a1 += alpha * f0.y;
            a2 += alpha * f1.x; a3 += alpha * f1.y;
        }
    }
    float4 r = make_float4(fmaxf(a0, 0.f), fmaxf(a1, 0.f), fmaxf(a2, 0.f), fmaxf(a3, 0.f));
    ((float4*)(g_h1 + (size_t)node * 128))[lane] = r;
}

__global__ void fused2_kernel(const float* __restrict__ b2, float* __restrict__ out) {
    __shared__ int   s_src[8][STAGE];
    __shared__ float s_e  [8][STAGE];
    int node = (blockIdx.x * blockDim.x + threadIdx.x) >> 5;
    int lane = threadIdx.x & 31;
    int wslot = (threadIdx.x >> 5);
    if (node >= N_NODES) return;
    int start = g_ptr[node], end = g_ptr[node + 1];
    int deg = end - start;
    bool sm = (deg <= STAGE);

    float adv = g_ad2[node];

    float den = 0.0f;
    for (int j = start + lane; j < end; j += 32) {
        int s = g_src_csr[j];
        float ev = expf(lrelu(g_as2[s] + adv));
        if (sm) {
            int k = j - start;
            s_src[wslot][k] = s;
            s_e[wslot][k] = ev;
        } else {
            g_e_csr[j] = ev;
        }
        den += ev;
    }
#pragma unroll
    for (int off = 16; off; off >>= 1)
        den += __shfl_xor_sync(0xffffffff, den, off);
    float rden = 1.0f / den;
    __syncwarp();

    float2 bv = ((const float2*)b2)[lane];
    float a0 = bv.x, a1 = bv.y;
    if (sm) {
#pragma unroll 4
        for (int k = 0; k < deg; k++) {
            int s = s_src[wslot][k];
            float alpha = s_e[wslot][k] * rden;
            float2 f = __half22float2(g_xl2h[(size_t)s * 32 + lane]);
            a0 += alpha * f.x; a1 += alpha * f.y;
        }
    } else {
        for (int j = start; j < end; j++) {
            int s = g_src_csr[j];
            float alpha = g_e_csr[j] * rden;
            float2 f = __half22float2(g_xl2h[(size_t)s * 32 + lane]);
            a0 += alpha * f.x; a1 += alpha * f.y;
        }
    }
    float2 r = make_float2(fmaxf(a0, 0.f), fmaxf(a1, 0.f));
    ((float2*)(out + (size_t)node * 64))[lane] = r;
}

// ---------------- launch ----------------
extern "C" void kernel_launch(void* const* d_in, const int* in_sizes, int n_in,
                              void* d_out, int out_size) {
    const float *x = 0, *W1 = 0, *W2 = 0;
    const void  *ei = 0;
    const float *v128[3] = {0, 0, 0};
    const float *v64 [3] = {0, 0, 0};
    int n128 = 0, n64 = 0;
    for (int i = 0; i < n_in; i++) {
        int sz = in_sizes[i];
        if      (sz == N_NODES * 128) x  = (const float*)d_in[i];
        else if (sz == 2 * N_EDGES)   ei = d_in[i];
        else if (sz == 128 * 128)     W1 = (const float*)d_in[i];
        else if (sz == 128 * 64)      W2 = (const float*)d_in[i];
        else if (sz == 128 && n128 < 3) v128[n128++] = (const float*)d_in[i];
        else if (sz == 64  && n64  < 3) v64 [n64++]  = (const float*)d_in[i];
    }
    const float* att_src1 = v128[0];
    const float* att_dst1 = v128[1];
    const float* b1       = v128[2];
    const float* att_src2 = v64[0];
    const float* att_dst2 = v64[1];
    const float* b2       = v64[2];
    float* out = (float*)d_out;

    const int TPB = 256;
    const int edge_blocks = (E_TOT + TPB - 1) / TPB;
    const int warp_blocks = (N_NODES * 32 + TPB - 1) / TPB;
    const int gemm_blocks = (N_NODES + 63) / 64;
    const int prep_blocks = (N_NODES + TPB - 1) / TPB;

    const int smem1 = (64 * XPITCH + 128 * 128) * 4;           // 99,328 B
    const int smem2 = (64 * XPITCH + 128 * 64) * 4;            // 66,560 B
    cudaFuncSetAttribute(gemm_kernel<128, 1, 32, 8>,
                         cudaFuncAttributeMaxDynamicSharedMemorySize, smem1);
    cudaFuncSetAttribute(gemm_kernel<64, 2, 16, 4>,
                         cudaFuncAttributeMaxDynamicSharedMemorySize, smem2);

    // fork/join: CSR chain on the capture (default) stream, gemm1 on s1.
    cudaStream_t s1;
    cudaStreamCreateWithFlags(&s1, cudaStreamNonBlocking);
    cudaEvent_t ev_fork, ev_gemm1;
    cudaEventCreateWithFlags(&ev_fork,  cudaEventDisableTiming);
    cudaEventCreateWithFlags(&ev_gemm1, cudaEventDisableTiming);

    cudaEventRecord(ev_fork, 0);
    cudaStreamWaitEvent(s1, ev_fork, 0);

    // branch A (capture stream): CSR by destination
    prep_kernel<<<prep_blocks, TPB>>>((const long long*)ei);
    hist_kernel<<<edge_blocks, TPB>>>(ei);
    scan_partial_kernel<<<NBLOCKS_SCAN, SBLK>>>();
    scan_final_kernel<<<NBLOCKS_SCAN, SBLK>>>();
    scatter_kernel<<<edge_blocks, TPB>>>(ei);

    // branch B (s1): layer-1 GEMM + fused attention logits
    gemm_kernel<128, 1, 32, 8><<<gemm_blocks, TPB, smem1, s1>>>(x, W1, att_src1, att_dst1);
    cudaEventRecord(ev_gemm1, s1);
    cudaStreamWaitEvent(0, ev_gemm1, 0);

    // join: rest sequential on the capture stream
    fused1_kernel<<<warp_blocks, TPB>>>(b1);
    gemm_kernel<64, 2, 16, 4><<<gemm_blocks, TPB, smem2>>>(x, W2, att_src2, att_dst2);
    fused2_kernel<<<warp_blocks, TPB>>>(b2, out);

    cudaEventDestroy(ev_fork);
    cudaEventDestroy(ev_gemm1);
    cudaStreamDestroy(s1);
}